// round 11
// baseline (speedup 1.0000x reference)
#include <cuda_runtime.h>
#include <cstdint>

// Gumbel-Sinkhorn, B=16, N=256, TAU=0.1, 100 iterations.
//
// Primal Sinkhorn-Knopp on the constant matrix E = exp(a/tau - m):
//   e[i] = 1 / sum_j E[i][j] * d[j]     (row normalize)
//   d[j] = 1 / sum_i E[i][j] * e[i]     (col normalize)
//   out  = E[i][j] * e[i] * d[j]
// R10: 4-CTA cluster, TWO matrices (A,B) per cluster interleaved so each
// matrix's exchange (scatter + fence + arrive + flight) hides behind the
// other's compute. 512 threads (16 warps): 4 rows/warp/matrix, E in ROW
// layout registers only (col partials fused from row sums, per R9).
// Exchange: 256 threads push 1 float to 3 peers via st.shared::cluster,
// published by fence.acq_rel.cluster + 3 remote mbarrier arrives (count=3,
// double-buffered parity). Named barrier (256 threads) for the publish step.

namespace {
constexpr int NMAT    = 16;
constexpr int N       = 256;
constexpr int CSZ     = 4;           // CTAs per cluster
constexpr int ROWS    = N / CSZ;     // 64 rows per CTA per matrix
constexpr int THREADS = 512;
constexpr int NWARP   = THREADS / 32;  // 16
constexpr int RPW     = ROWS / NWARP;  // 4 rows per warp per matrix
constexpr int NITER   = 100;
constexpr float INV_TAU = 10.0f;
}

__device__ __forceinline__ uint32_t smem_u32(const void* p) {
    return (uint32_t)__cvta_generic_to_shared(p);
}

__device__ __forceinline__ uint32_t mapa_rank(uint32_t laddr, uint32_t rank) {
    uint32_t rem;
    asm volatile("mapa.shared::cluster.u32 %0, %1, %2;" : "=r"(rem) : "r"(laddr), "r"(rank));
    return rem;
}

__device__ __forceinline__ void st_cluster_f32_addr(uint32_t raddr, float v) {
    asm volatile("st.shared::cluster.f32 [%0], %1;" :: "r"(raddr), "f"(v) : "memory");
}

__device__ __forceinline__ void st_cluster_f32(uint32_t laddr, uint32_t rank, float v) {
    st_cluster_f32_addr(mapa_rank(laddr, rank), v);
}

__device__ __forceinline__ void mbar_arrive_cluster(uint32_t raddr) {
    asm volatile("mbarrier.arrive.shared::cluster.b64 _, [%0];" :: "r"(raddr) : "memory");
}

__device__ __forceinline__ void mbar_wait(uint32_t addr, uint32_t phase) {
    asm volatile(
        "{\n\t"
        ".reg .pred P;\n\t"
        "WLOOP_%=:\n\t"
        "mbarrier.try_wait.parity.acquire.cluster.shared::cta.b64 P, [%0], %1, 0x989680;\n\t"
        "@P bra WDONE_%=;\n\t"
        "bra WLOOP_%=;\n\t"
        "WDONE_%=:\n\t"
        "}"
        :: "r"(addr), "r"(phase) : "memory");
}

__device__ __forceinline__ void fence_cluster() {
    asm volatile("fence.acq_rel.cluster;" ::: "memory");
}

__device__ __forceinline__ void named_bar_256() {
    asm volatile("bar.sync 1, 256;" ::: "memory");
}

__device__ __forceinline__ void cluster_sync_all() {
    asm volatile("barrier.cluster.arrive.aligned;" ::: "memory");
    asm volatile("barrier.cluster.wait.aligned;" ::: "memory");
}

__global__ void __launch_bounds__(THREADS, 1) __cluster_dims__(CSZ, 1, 1)
sinkhorn_kernel(const float* __restrict__ A, float* __restrict__ Out)
{
    __shared__ __align__(16) float dA[N], dB[N];
    __shared__ __align__(16) float wsA[NWARP][N], wsB[NWARP][N];   // 32 KB
    __shared__ __align__(16) float xA[2][CSZ][N], xB[2][CSZ][N];   // 16 KB
    __shared__ __align__(8) unsigned long long mbA[2], mbB[2];
    __shared__ float redA[NWARP], redB[NWARP];
    __shared__ float mbuf[2][CSZ];

    const int tid  = threadIdx.x;
    const int w    = tid >> 5;
    const int l    = tid & 31;
    const int rank = blockIdx.x & (CSZ - 1);
    const int cl   = blockIdx.x >> 2;   // cluster id: matrices 2cl, 2cl+1

    const float* AmA = A   + (size_t)(2 * cl)     * N * N;
    const float* AmB = A   + (size_t)(2 * cl + 1) * N * N;
    float*       OmA = Out + (size_t)(2 * cl)     * N * N;
    float*       OmB = Out + (size_t)(2 * cl + 1) * N * N;

    if (tid == 0) {
        #pragma unroll
        for (int q = 0; q < 2; q++) {
            asm volatile("mbarrier.init.shared.b64 [%0], %1;"
                         :: "r"(smem_u32(&mbA[q])), "r"(CSZ - 1) : "memory");
            asm volatile("mbarrier.init.shared.b64 [%0], %1;"
                         :: "r"(smem_u32(&mbB[q])), "r"(CSZ - 1) : "memory");
        }
        asm volatile("fence.mbarrier_init.release.cluster;" ::: "memory");
    }

    // ---- row layout: warp w owns local rows [4w,4w+4); lane l cols [8l,8l+8)
    const int c0   = l * 8;
    const int grow = rank * ROWS + RPW * w;

    float erA[32], erB[32];   // [row r: 8 cols] x 4 rows
    #pragma unroll
    for (int r = 0; r < RPW; r++) {
        float4 a0 = *(const float4*)(AmA + (grow + r) * N + c0);
        float4 a1 = *(const float4*)(AmA + (grow + r) * N + c0 + 4);
        erA[r*8+0]=a0.x; erA[r*8+1]=a0.y; erA[r*8+2]=a0.z; erA[r*8+3]=a0.w;
        erA[r*8+4]=a1.x; erA[r*8+5]=a1.y; erA[r*8+6]=a1.z; erA[r*8+7]=a1.w;
        float4 b0 = *(const float4*)(AmB + (grow + r) * N + c0);
        float4 b1 = *(const float4*)(AmB + (grow + r) * N + c0 + 4);
        erB[r*8+0]=b0.x; erB[r*8+1]=b0.y; erB[r*8+2]=b0.z; erB[r*8+3]=b0.w;
        erB[r*8+4]=b1.x; erB[r*8+5]=b1.y; erB[r*8+6]=b1.z; erB[r*8+7]=b1.w;
    }
    #pragma unroll
    for (int k = 0; k < 32; k++) { erA[k] *= INV_TAU; erB[k] *= INV_TAU; }

    // ---- per-matrix global max
    {
        float ma = erA[0], mb = erB[0];
        #pragma unroll
        for (int k = 1; k < 32; k++) { ma = fmaxf(ma, erA[k]); mb = fmaxf(mb, erB[k]); }
        #pragma unroll
        for (int off = 16; off; off >>= 1) {
            ma = fmaxf(ma, __shfl_xor_sync(0xffffffffu, ma, off));
            mb = fmaxf(mb, __shfl_xor_sync(0xffffffffu, mb, off));
        }
        if (l == 0) { redA[w] = ma; redB[w] = mb; }
    }
    __syncthreads();
    if (w < 2) {
        float v = (l < NWARP) ? ((w == 0) ? redA[l] : redB[l]) : -3.4e38f;
        #pragma unroll
        for (int off = 16; off; off >>= 1)
            v = fmaxf(v, __shfl_xor_sync(0xffffffffu, v, off));
        if (l == 0) {
            uint32_t slot = smem_u32(&mbuf[w][rank]);
            #pragma unroll
            for (int r = 0; r < CSZ; r++) st_cluster_f32(slot, r, v);
        }
    }
    cluster_sync_all();   // orders mbuf stores AND mbarrier inits cluster-wide
    float mA = mbuf[0][0], mB = mbuf[1][0];
    #pragma unroll
    for (int r = 1; r < CSZ; r++) { mA = fmaxf(mA, mbuf[0][r]); mB = fmaxf(mB, mbuf[1][r]); }

    #pragma unroll
    for (int k = 0; k < 32; k++) {
        erA[k] = __expf(erA[k] - mA);
        erB[k] = __expf(erB[k] - mB);
    }

    if (tid < N) { dA[tid] = 1.0f; dB[tid] = 1.0f; }
    __syncthreads();

    // ---- hoisted remote addresses
    const uint32_t mbA_local = smem_u32(&mbA[0]);
    const uint32_t mbB_local = smem_u32(&mbB[0]);
    uint32_t rsxA[CSZ - 1], rsxB[CSZ - 1];
    if (tid < N) {
        uint32_t la = smem_u32(&xA[0][rank][tid]);
        uint32_t lb = smem_u32(&xB[0][rank][tid]);
        #pragma unroll
        for (int i = 0; i < CSZ - 1; i++) {
            uint32_t pr = (uint32_t)((rank + 1 + i) & (CSZ - 1));
            rsxA[i] = mapa_rank(la, pr);
            rsxB[i] = mapa_rank(lb, pr);
        }
    }
    uint32_t rmbA = 0, rmbB = 0;
    if (w == 0 && l < CSZ - 1) {
        uint32_t pr = (uint32_t)((rank + 1 + l) & (CSZ - 1));
        rmbA = mapa_rank(mbA_local, pr);
        rmbB = mapa_rank(mbB_local, pr);
    }
    const int p0 = (rank + 1) & (CSZ - 1);
    const int p1 = (rank + 2) & (CSZ - 1);
    const int p2 = (rank + 3) & (CSZ - 1);

    float rsA[RPW], rsB[RPW];
    #pragma unroll
    for (int r = 0; r < RPW; r++) { rsA[r] = 1.0f; rsB[r] = 1.0f; }

    #pragma unroll 1
    for (int it = 0; it < NITER; it++) {
        const uint32_t par  = (uint32_t)(it & 1);
        const uint32_t ph   = (uint32_t)((it >> 1) & 1);
        const uint32_t poff = par * (CSZ * N * 4u);

        // ======== A: row pass + fused col partials ========
        {
            float4 d0 = *(const float4*)&dA[c0];
            float4 d1 = *(const float4*)&dA[c0 + 4];
            float s[RPW];
            #pragma unroll
            for (int r = 0; r < RPW; r++)
                s[r] = erA[r*8+0]*d0.x + erA[r*8+1]*d0.y + erA[r*8+2]*d0.z + erA[r*8+3]*d0.w
                     + erA[r*8+4]*d1.x + erA[r*8+5]*d1.y + erA[r*8+6]*d1.z + erA[r*8+7]*d1.w;
            #pragma unroll
            for (int off = 16; off; off >>= 1) {
                #pragma unroll
                for (int r = 0; r < RPW; r++)
                    s[r] += __shfl_xor_sync(0xffffffffu, s[r], off);
            }
            #pragma unroll
            for (int r = 0; r < RPW; r++)
                rsA[r] = __fdividef(1.0f, fmaxf(s[r], 1e-30f));
            float4 q0, q1;
            q0.x = erA[0]*rsA[0] + erA[8]*rsA[1] + erA[16]*rsA[2] + erA[24]*rsA[3];
            q0.y = erA[1]*rsA[0] + erA[9]*rsA[1] + erA[17]*rsA[2] + erA[25]*rsA[3];
            q0.z = erA[2]*rsA[0] + erA[10]*rsA[1] + erA[18]*rsA[2] + erA[26]*rsA[3];
            q0.w = erA[3]*rsA[0] + erA[11]*rsA[1] + erA[19]*rsA[2] + erA[27]*rsA[3];
            q1.x = erA[4]*rsA[0] + erA[12]*rsA[1] + erA[20]*rsA[2] + erA[28]*rsA[3];
            q1.y = erA[5]*rsA[0] + erA[13]*rsA[1] + erA[21]*rsA[2] + erA[29]*rsA[3];
            q1.z = erA[6]*rsA[0] + erA[14]*rsA[1] + erA[22]*rsA[2] + erA[30]*rsA[3];
            q1.w = erA[7]*rsA[0] + erA[15]*rsA[1] + erA[23]*rsA[2] + erA[31]*rsA[3];
            *(float4*)&wsA[w][c0]     = q0;
            *(float4*)&wsA[w][c0 + 4] = q1;
        }
        __syncthreads();   // wsA ready

        // ======== A: local colsum + scatter (warps 0-7) ========
        float pownA = 0.0f;
        if (tid < N) {
            float f0 = 0.f, f1 = 0.f, f2 = 0.f, f3 = 0.f;
            #pragma unroll
            for (int w2 = 0; w2 < NWARP; w2 += 4) {
                f0 += wsA[w2][tid];     f1 += wsA[w2 + 1][tid];
                f2 += wsA[w2 + 2][tid]; f3 += wsA[w2 + 3][tid];
            }
            pownA = (f0 + f1) + (f2 + f3);
            #pragma unroll
            for (int i = 0; i < CSZ - 1; i++)
                st_cluster_f32_addr(rsxA[i] + poff, pownA);
            named_bar_256();   // scatter stores from warps 0-7 CTA-visible
            if (w == 0 && l < CSZ - 1) {
                fence_cluster();
                mbar_arrive_cluster(rmbA + par * 8);
            }
        }

        // ======== B: row pass + fused col partials ========
        {
            float4 d0 = *(const float4*)&dB[c0];
            float4 d1 = *(const float4*)&dB[c0 + 4];
            float s[RPW];
            #pragma unroll
            for (int r = 0; r < RPW; r++)
                s[r] = erB[r*8+0]*d0.x + erB[r*8+1]*d0.y + erB[r*8+2]*d0.z + erB[r*8+3]*d0.w
                     + erB[r*8+4]*d1.x + erB[r*8+5]*d1.y + erB[r*8+6]*d1.z + erB[r*8+7]*d1.w;
            #pragma unroll
            for (int off = 16; off; off >>= 1) {
                #pragma unroll
                for (int r = 0; r < RPW; r++)
                    s[r] += __shfl_xor_sync(0xffffffffu, s[r], off);
            }
            #pragma unroll
            for (int r = 0; r < RPW; r++)
                rsB[r] = __fdividef(1.0f, fmaxf(s[r], 1e-30f));
            float4 q0, q1;
            q0.x = erB[0]*rsB[0] + erB[8]*rsB[1] + erB[16]*rsB[2] + erB[24]*rsB[3];
            q0.y = erB[1]*rsB[0] + erB[9]*rsB[1] + erB[17]*rsB[2] + erB[25]*rsB[3];
            q0.z = erB[2]*rsB[0] + erB[10]*rsB[1] + erB[18]*rsB[2] + erB[26]*rsB[3];
            q0.w = erB[3]*rsB[0] + erB[11]*rsB[1] + erB[19]*rsB[2] + erB[27]*rsB[3];
            q1.x = erB[4]*rsB[0] + erB[12]*rsB[1] + erB[20]*rsB[2] + erB[28]*rsB[3];
            q1.y = erB[5]*rsB[0] + erB[13]*rsB[1] + erB[21]*rsB[2] + erB[29]*rsB[3];
            q1.z = erB[6]*rsB[0] + erB[14]*rsB[1] + erB[22]*rsB[2] + erB[30]*rsB[3];
            q1.w = erB[7]*rsB[0] + erB[15]*rsB[1] + erB[23]*rsB[2] + erB[31]*rsB[3];
            *(float4*)&wsB[w][c0]     = q0;
            *(float4*)&wsB[w][c0 + 4] = q1;
        }
        __syncthreads();   // wsB ready

        // ======== B: colsum + scatter, then combine A and B (warps 0-7) ====
        if (tid < N) {
            float f0 = 0.f, f1 = 0.f, f2 = 0.f, f3 = 0.f;
            #pragma unroll
            for (int w2 = 0; w2 < NWARP; w2 += 4) {
                f0 += wsB[w2][tid];     f1 += wsB[w2 + 1][tid];
                f2 += wsB[w2 + 2][tid]; f3 += wsB[w2 + 3][tid];
            }
            float pownB = (f0 + f1) + (f2 + f3);
            #pragma unroll
            for (int i = 0; i < CSZ - 1; i++)
                st_cluster_f32_addr(rsxB[i] + poff, pownB);
            named_bar_256();
            if (w == 0 && l < CSZ - 1) {
                fence_cluster();
                mbar_arrive_cluster(rmbB + par * 8);
            }

            // combine A (its exchange has been in flight for a whole phase)
            mbar_wait(mbA_local + par * 8, ph);
            float fa = pownA + xA[par][p0][tid] + xA[par][p1][tid] + xA[par][p2][tid];
            dA[tid] = __fdividef(1.0f, fmaxf(fa, 1e-30f));

            // combine B
            mbar_wait(mbB_local + par * 8, ph);
            float fb = pownB + xB[par][p0][tid] + xB[par][p1][tid] + xB[par][p2][tid];
            dB[tid] = __fdividef(1.0f, fmaxf(fb, 1e-30f));
        }
        __syncthreads();   // dA, dB ready for next iteration
    }

    // ======== epilogue: P = E * e[i] * d[j] for both matrices ========
    {
        float4 d0 = *(const float4*)&dA[c0];
        float4 d1 = *(const float4*)&dA[c0 + 4];
        #pragma unroll
        for (int r = 0; r < RPW; r++) {
            float4 o;
            o.x = erA[r*8+0]*rsA[r]*d0.x; o.y = erA[r*8+1]*rsA[r]*d0.y;
            o.z = erA[r*8+2]*rsA[r]*d0.z; o.w = erA[r*8+3]*rsA[r]*d0.w;
            *(float4*)(OmA + (grow + r) * N + c0) = o;
            o.x = erA[r*8+4]*rsA[r]*d1.x; o.y = erA[r*8+5]*rsA[r]*d1.y;
            o.z = erA[r*8+6]*rsA[r]*d1.z; o.w = erA[r*8+7]*rsA[r]*d1.w;
            *(float4*)(OmA + (grow + r) * N + c0 + 4) = o;
        }
    }
    {
        float4 d0 = *(const float4*)&dB[c0];
        float4 d1 = *(const float4*)&dB[c0 + 4];
        #pragma unroll
        for (int r = 0; r < RPW; r++) {
            float4 o;
            o.x = erB[r*8+0]*rsB[r]*d0.x; o.y = erB[r*8+1]*rsB[r]*d0.y;
            o.z = erB[r*8+2]*rsB[r]*d0.z; o.w = erB[r*8+3]*rsB[r]*d0.w;
            *(float4*)(OmB + (grow + r) * N + c0) = o;
            o.x = erB[r*8+4]*rsB[r]*d1.x; o.y = erB[r*8+5]*rsB[r]*d1.y;
            o.z = erB[r*8+6]*rsB[r]*d1.z; o.w = erB[r*8+7]*rsB[r]*d1.w;
            *(float4*)(OmB + (grow + r) * N + c0 + 4) = o;
        }
    }

    // keep all CTAs alive until every in-flight remote store is consumed
    cluster_sync_all();
}

extern "C" void kernel_launch(void* const* d_in, const int* in_sizes, int n_in,
                              void* d_out, int out_size) {
    const float* alpha = (const float*)d_in[0];
    float* out = (float*)d_out;
    sinkhorn_kernel<<<(NMAT / 2) * CSZ, THREADS>>>(alpha, out);
}

// round 12
// speedup vs baseline: 1.0499x; 1.0499x over previous
#include <cuda_runtime.h>
#include <cstdint>

// Gumbel-Sinkhorn, B=16, N=256, TAU=0.1, 100 iterations.
//
// Primal Sinkhorn-Knopp on the constant matrix E = exp(a/tau - m):
//   e[i] = 1 / sum_j E[i][j] * d[j]     (row normalize)
//   d[j] = 1 / sum_i E[i][j] * e[i]     (col normalize)
//   out  = E[i][j] * e[i] * d[j]
// R11: 8-CTA cluster, TWO matrices (A,B) interleaved per cluster (R8 topology,
// 1 row/warp/matrix -> only 16 E regs) with R9's scalar-scatter exchange
// (st.shared::cluster + fence + remote mbarrier arrive, count=7, double
// buffered) and R9's fused col partials. A's DSMEM flight hides behind B's
// reduction and vice versa. Dynamic SMEM (~99KB).

namespace {
constexpr int NMAT    = 16;
constexpr int N       = 256;
constexpr int CSZ     = 8;            // CTAs per cluster
constexpr int ROWS    = N / CSZ;      // 32 rows per CTA per matrix
constexpr int THREADS = 1024;
constexpr int NWARP   = 32;
constexpr int NITER   = 100;
constexpr float INV_TAU = 10.0f;

// dynamic smem layout (bytes)
constexpr uint32_t OFF_DA   = 0;                    // float dA[256]
constexpr uint32_t OFF_DB   = 1024;                 // float dB[256]
constexpr uint32_t OFF_XA   = 2048;                 // float xA[2][8][256]
constexpr uint32_t OFF_XB   = OFF_XA + 16384;       // float xB[2][8][256]
constexpr uint32_t OFF_WSA  = OFF_XB + 16384;       // float wsA[32][256]
constexpr uint32_t OFF_WSB  = OFF_WSA + 32768;      // float wsB[32][256]
constexpr uint32_t OFF_MBA  = OFF_WSB + 32768;      // u64 mbA[2]
constexpr uint32_t OFF_MBB  = OFF_MBA + 16;         // u64 mbB[2]
constexpr uint32_t OFF_RED  = OFF_MBB + 16;         // float redA[32], redB[32]
constexpr uint32_t OFF_MAXB = OFF_RED + 256;        // float mbuf[2][8]
constexpr uint32_t SMEM_TOTAL = OFF_MAXB + 64;      // ~100.7 KB
constexpr uint32_t D_AB = OFF_XB - OFF_XA;          // xA slot -> xB slot delta
constexpr uint32_t D_MB = OFF_MBB - OFF_MBA;        // mbA -> mbB delta
}

__device__ __forceinline__ uint32_t smem_u32(const void* p) {
    return (uint32_t)__cvta_generic_to_shared(p);
}

__device__ __forceinline__ uint32_t mapa_rank(uint32_t laddr, uint32_t rank) {
    uint32_t rem;
    asm volatile("mapa.shared::cluster.u32 %0, %1, %2;" : "=r"(rem) : "r"(laddr), "r"(rank));
    return rem;
}

__device__ __forceinline__ void st_cluster_f32_addr(uint32_t raddr, float v) {
    asm volatile("st.shared::cluster.f32 [%0], %1;" :: "r"(raddr), "f"(v) : "memory");
}

__device__ __forceinline__ void mbar_arrive_cluster(uint32_t raddr) {
    asm volatile("mbarrier.arrive.shared::cluster.b64 _, [%0];" :: "r"(raddr) : "memory");
}

__device__ __forceinline__ void mbar_wait(uint32_t addr, uint32_t phase) {
    asm volatile(
        "{\n\t"
        ".reg .pred P;\n\t"
        "WLOOP_%=:\n\t"
        "mbarrier.try_wait.parity.acquire.cluster.shared::cta.b64 P, [%0], %1, 0x989680;\n\t"
        "@P bra WDONE_%=;\n\t"
        "bra WLOOP_%=;\n\t"
        "WDONE_%=:\n\t"
        "}"
        :: "r"(addr), "r"(phase) : "memory");
}

__device__ __forceinline__ void fence_cluster() {
    asm volatile("fence.acq_rel.cluster;" ::: "memory");
}

__device__ __forceinline__ void cluster_sync_all() {
    asm volatile("barrier.cluster.arrive.aligned;" ::: "memory");
    asm volatile("barrier.cluster.wait.aligned;" ::: "memory");
}

__global__ void __launch_bounds__(THREADS, 1) __cluster_dims__(CSZ, 1, 1)
sinkhorn_kernel(const float* __restrict__ A, float* __restrict__ Out)
{
    extern __shared__ __align__(16) char smem[];
    float* dAp  = reinterpret_cast<float*>(smem + OFF_DA);
    float* dBp  = reinterpret_cast<float*>(smem + OFF_DB);
    float* xAp  = reinterpret_cast<float*>(smem + OFF_XA);   // [2][8][256]
    float* xBp  = reinterpret_cast<float*>(smem + OFF_XB);
    float* wsAp = reinterpret_cast<float*>(smem + OFF_WSA);  // [32][256]
    float* wsBp = reinterpret_cast<float*>(smem + OFF_WSB);
    float* redA = reinterpret_cast<float*>(smem + OFF_RED);
    float* redB = redA + NWARP;
    float* mxb  = reinterpret_cast<float*>(smem + OFF_MAXB); // [2][8]

    const uint32_t sbase = smem_u32(smem);
    const int tid  = threadIdx.x;
    const int w    = tid >> 5;
    const int l    = tid & 31;
    const int rank = blockIdx.x & (CSZ - 1);
    const int cl   = blockIdx.x >> 3;   // cluster id: matrices 2cl, 2cl+1

    const float* AmA = A   + (size_t)(2 * cl)     * N * N;
    const float* AmB = A   + (size_t)(2 * cl + 1) * N * N;
    float*       OmA = Out + (size_t)(2 * cl)     * N * N;
    float*       OmB = Out + (size_t)(2 * cl + 1) * N * N;

    if (tid == 0) {
        #pragma unroll
        for (int q = 0; q < 2; q++) {
            asm volatile("mbarrier.init.shared.b64 [%0], %1;"
                         :: "r"(sbase + OFF_MBA + q * 8), "r"(CSZ - 1) : "memory");
            asm volatile("mbarrier.init.shared.b64 [%0], %1;"
                         :: "r"(sbase + OFF_MBB + q * 8), "r"(CSZ - 1) : "memory");
        }
        asm volatile("fence.mbarrier_init.release.cluster;" ::: "memory");
    }

    // ---- row layout: warp w owns global row rank*32+w; lane l cols [8l,8l+8)
    const int grow = rank * ROWS + w;
    const int c0   = l * 8;

    float erA[8], erB[8];
    {
        float4 a0 = *(const float4*)(AmA + grow * N + c0);
        float4 a1 = *(const float4*)(AmA + grow * N + c0 + 4);
        erA[0]=a0.x; erA[1]=a0.y; erA[2]=a0.z; erA[3]=a0.w;
        erA[4]=a1.x; erA[5]=a1.y; erA[6]=a1.z; erA[7]=a1.w;
        float4 b0 = *(const float4*)(AmB + grow * N + c0);
        float4 b1 = *(const float4*)(AmB + grow * N + c0 + 4);
        erB[0]=b0.x; erB[1]=b0.y; erB[2]=b0.z; erB[3]=b0.w;
        erB[4]=b1.x; erB[5]=b1.y; erB[6]=b1.z; erB[7]=b1.w;
        #pragma unroll
        for (int k = 0; k < 8; k++) { erA[k] *= INV_TAU; erB[k] *= INV_TAU; }
    }

    // ---- per-matrix global max (stable E = exp(a/tau - m))
    {
        float ma = erA[0], mb = erB[0];
        #pragma unroll
        for (int k = 1; k < 8; k++) { ma = fmaxf(ma, erA[k]); mb = fmaxf(mb, erB[k]); }
        #pragma unroll
        for (int off = 16; off; off >>= 1) {
            ma = fmaxf(ma, __shfl_xor_sync(0xffffffffu, ma, off));
            mb = fmaxf(mb, __shfl_xor_sync(0xffffffffu, mb, off));
        }
        if (l == 0) { redA[w] = ma; redB[w] = mb; }
    }
    __syncthreads();
    if (w < 2) {
        float v = (w == 0) ? redA[l] : redB[l];
        #pragma unroll
        for (int off = 16; off; off >>= 1)
            v = fmaxf(v, __shfl_xor_sync(0xffffffffu, v, off));
        if (l == 0) {
            uint32_t slot = sbase + OFF_MAXB + (w * CSZ + rank) * 4;
            #pragma unroll
            for (int r = 0; r < CSZ; r++)
                st_cluster_f32_addr(mapa_rank(slot, (uint32_t)r), v);
        }
    }
    cluster_sync_all();   // orders max stores AND mbarrier inits cluster-wide
    float mA = mxb[0], mB = mxb[CSZ];
    #pragma unroll
    for (int r = 1; r < CSZ; r++) { mA = fmaxf(mA, mxb[r]); mB = fmaxf(mB, mxb[CSZ + r]); }

    #pragma unroll
    for (int k = 0; k < 8; k++) {
        erA[k] = __expf(erA[k] - mA);
        erB[k] = __expf(erB[k] - mB);
    }

    if (tid < N) { dAp[tid] = 1.0f; dBp[tid] = 1.0f; }
    __syncthreads();

    // ---- hoisted remote addresses
    // scatter bases: thread j (<256) pushes its col partial to 7 peers.
    // mapa is offset-preserving within a CTA's window, so xB/parity targets
    // derive from the xA base by constant deltas.
    uint32_t sA[CSZ - 1];
    if (tid < N) {
        uint32_t la = sbase + OFF_XA + (uint32_t)rank * 1024u + (uint32_t)tid * 4u;
        #pragma unroll
        for (int i = 0; i < CSZ - 1; i++)
            sA[i] = mapa_rank(la, (uint32_t)((rank + 1 + i) & (CSZ - 1)));
    }
    uint32_t rmbA = 0;
    if (w == 0 && l < CSZ - 1)
        rmbA = mapa_rank(sbase + OFF_MBA, (uint32_t)((rank + 1 + l) & (CSZ - 1)));

    float rsA = 1.0f, rsB = 1.0f;   // 1/rowsum for my row (persist for epilogue)

    #pragma unroll 1
    for (int it = 0; it < NITER; it++) {
        const uint32_t par    = (uint32_t)(it & 1);
        const uint32_t ph     = (uint32_t)((it >> 1) & 1);
        const uint32_t paroff = par * 8192u;   // [2][8][256] parity stride

        // ======== P1: A row pass + fused col partials ========
        {
            float4 d0 = *(const float4*)&dAp[c0];
            float4 d1 = *(const float4*)&dAp[c0 + 4];
            float s = erA[0]*d0.x + erA[1]*d0.y + erA[2]*d0.z + erA[3]*d0.w
                    + erA[4]*d1.x + erA[5]*d1.y + erA[6]*d1.z + erA[7]*d1.w;
            #pragma unroll
            for (int off = 16; off; off >>= 1)
                s += __shfl_xor_sync(0xffffffffu, s, off);
            rsA = __fdividef(1.0f, fmaxf(s, 1e-30f));
            float4 q0, q1;
            q0.x = erA[0]*rsA; q0.y = erA[1]*rsA; q0.z = erA[2]*rsA; q0.w = erA[3]*rsA;
            q1.x = erA[4]*rsA; q1.y = erA[5]*rsA; q1.z = erA[6]*rsA; q1.w = erA[7]*rsA;
            *(float4*)&wsAp[w * N + c0]     = q0;
            *(float4*)&wsAp[w * N + c0 + 4] = q1;
        }
        __syncthreads();

        // ======== P2: B row pass (all warps) || colsumA + scatterA (w 0-7) ==
        {
            float4 d0 = *(const float4*)&dBp[c0];
            float4 d1 = *(const float4*)&dBp[c0 + 4];
            float s = erB[0]*d0.x + erB[1]*d0.y + erB[2]*d0.z + erB[3]*d0.w
                    + erB[4]*d1.x + erB[5]*d1.y + erB[6]*d1.z + erB[7]*d1.w;
            #pragma unroll
            for (int off = 16; off; off >>= 1)
                s += __shfl_xor_sync(0xffffffffu, s, off);
            rsB = __fdividef(1.0f, fmaxf(s, 1e-30f));
            float4 q0, q1;
            q0.x = erB[0]*rsB; q0.y = erB[1]*rsB; q0.z = erB[2]*rsB; q0.w = erB[3]*rsB;
            q1.x = erB[4]*rsB; q1.y = erB[5]*rsB; q1.z = erB[6]*rsB; q1.w = erB[7]*rsB;
            *(float4*)&wsBp[w * N + c0]     = q0;
            *(float4*)&wsBp[w * N + c0 + 4] = q1;
        }
        float pownA = 0.0f;
        if (tid < N) {
            float f0 = 0.f, f1 = 0.f, f2 = 0.f, f3 = 0.f;
            #pragma unroll
            for (int w2 = 0; w2 < NWARP; w2 += 4) {
                f0 += wsAp[w2 * N + tid];       f1 += wsAp[(w2 + 1) * N + tid];
                f2 += wsAp[(w2 + 2) * N + tid]; f3 += wsAp[(w2 + 3) * N + tid];
            }
            pownA = (f0 + f1) + (f2 + f3);
            #pragma unroll
            for (int i = 0; i < CSZ - 1; i++)
                st_cluster_f32_addr(sA[i] + paroff, pownA);
        }
        __syncthreads();

        // ======== P3: publish A || colsumB + scatterB ========
        if (w == 0 && l < CSZ - 1) {
            fence_cluster();
            mbar_arrive_cluster(rmbA + par * 8);
        }
        float pownB = 0.0f;
        if (tid < N) {
            float f0 = 0.f, f1 = 0.f, f2 = 0.f, f3 = 0.f;
            #pragma unroll
            for (int w2 = 0; w2 < NWARP; w2 += 4) {
                f0 += wsBp[w2 * N + tid];       f1 += wsBp[(w2 + 1) * N + tid];
                f2 += wsBp[(w2 + 2) * N + tid]; f3 += wsBp[(w2 + 3) * N + tid];
            }
            pownB = (f0 + f1) + (f2 + f3);
            #pragma unroll
            for (int i = 0; i < CSZ - 1; i++)
                st_cluster_f32_addr(sA[i] + D_AB + paroff, pownB);
        }
        __syncthreads();

        // ======== P4: publish B || combine A then B (warps 0-7) ========
        if (w == 0 && l < CSZ - 1) {
            fence_cluster();
            mbar_arrive_cluster(rmbA + D_MB + par * 8);
        }
        if (tid < N) {
            // A's exchange has been in flight since P3 start -> near-free wait
            mbar_wait(sbase + OFF_MBA + par * 8, ph);
            float fa = pownA;
            #pragma unroll
            for (int i = 1; i < CSZ; i++) {
                int src = (rank + i) & (CSZ - 1);
                fa += xAp[paroff / 4 + src * N + tid];
            }
            dAp[tid] = __fdividef(1.0f, fmaxf(fa, 1e-30f));

            mbar_wait(sbase + OFF_MBB + par * 8, ph);
            float fb = pownB;
            #pragma unroll
            for (int i = 1; i < CSZ; i++) {
                int src = (rank + i) & (CSZ - 1);
                fb += xBp[paroff / 4 + src * N + tid];
            }
            dBp[tid] = __fdividef(1.0f, fmaxf(fb, 1e-30f));
        }
        __syncthreads();
    }

    // ======== epilogue: P = E * e[i] * d[j] for both matrices ========
    {
        float4 d0 = *(const float4*)&dAp[c0];
        float4 d1 = *(const float4*)&dAp[c0 + 4];
        float4 o0, o1;
        o0.x = erA[0]*rsA*d0.x; o0.y = erA[1]*rsA*d0.y;
        o0.z = erA[2]*rsA*d0.z; o0.w = erA[3]*rsA*d0.w;
        o1.x = erA[4]*rsA*d1.x; o1.y = erA[5]*rsA*d1.y;
        o1.z = erA[6]*rsA*d1.z; o1.w = erA[7]*rsA*d1.w;
        *(float4*)(OmA + grow * N + c0)     = o0;
        *(float4*)(OmA + grow * N + c0 + 4) = o1;
    }
    {
        float4 d0 = *(const float4*)&dBp[c0];
        float4 d1 = *(const float4*)&dBp[c0 + 4];
        float4 o0, o1;
        o0.x = erB[0]*rsB*d0.x; o0.y = erB[1]*rsB*d0.y;
        o0.z = erB[2]*rsB*d0.z; o0.w = erB[3]*rsB*d0.w;
        o1.x = erB[4]*rsB*d1.x; o1.y = erB[5]*rsB*d1.y;
        o1.z = erB[6]*rsB*d1.z; o1.w = erB[7]*rsB*d1.w;
        *(float4*)(OmB + grow * N + c0)     = o0;
        *(float4*)(OmB + grow * N + c0 + 4) = o1;
    }

    // keep all CTAs alive until every in-flight remote store is consumed
    cluster_sync_all();
}

extern "C" void kernel_launch(void* const* d_in, const int* in_sizes, int n_in,
                              void* d_out, int out_size) {
    const float* alpha = (const float*)d_in[0];
    float* out = (float*)d_out;
    cudaFuncSetAttribute(sinkhorn_kernel,
                         cudaFuncAttributeMaxDynamicSharedMemorySize, SMEM_TOTAL);
    sinkhorn_kernel<<<(NMAT / 2) * CSZ, THREADS, SMEM_TOTAL>>>(alpha, out);
}

// round 13
// speedup vs baseline: 1.0508x; 1.0009x over previous
#include <cuda_runtime.h>
#include <cstdint>

// Gumbel-Sinkhorn, B=16, N=256, TAU=0.1, 100 iterations.
//
// Primal Sinkhorn-Knopp on the constant matrix E = exp(a/tau - m):
//   e[i] = 1 / sum_j E[i][j] * d[j]     (row normalize)
//   d[j] = 1 / sum_i E[i][j] * e[i]     (col normalize)
//   out  = E[i][j] * e[i] * d[j]
// R11: 8-CTA cluster, TWO matrices (A,B) interleaved per cluster (R8 topology,
// 1 row/warp/matrix -> only 16 E regs) with R9's scalar-scatter exchange
// (st.shared::cluster + fence + remote mbarrier arrive, count=7, double
// buffered) and R9's fused col partials. A's DSMEM flight hides behind B's
// reduction and vice versa. Dynamic SMEM (~99KB).

namespace {
constexpr int NMAT    = 16;
constexpr int N       = 256;
constexpr int CSZ     = 8;            // CTAs per cluster
constexpr int ROWS    = N / CSZ;      // 32 rows per CTA per matrix
constexpr int THREADS = 1024;
constexpr int NWARP   = 32;
constexpr int NITER   = 100;
constexpr float INV_TAU = 10.0f;

// dynamic smem layout (bytes)
constexpr uint32_t OFF_DA   = 0;                    // float dA[256]
constexpr uint32_t OFF_DB   = 1024;                 // float dB[256]
constexpr uint32_t OFF_XA   = 2048;                 // float xA[2][8][256]
constexpr uint32_t OFF_XB   = OFF_XA + 16384;       // float xB[2][8][256]
constexpr uint32_t OFF_WSA  = OFF_XB + 16384;       // float wsA[32][256]
constexpr uint32_t OFF_WSB  = OFF_WSA + 32768;      // float wsB[32][256]
constexpr uint32_t OFF_MBA  = OFF_WSB + 32768;      // u64 mbA[2]
constexpr uint32_t OFF_MBB  = OFF_MBA + 16;         // u64 mbB[2]
constexpr uint32_t OFF_RED  = OFF_MBB + 16;         // float redA[32], redB[32]
constexpr uint32_t OFF_MAXB = OFF_RED + 256;        // float mbuf[2][8]
constexpr uint32_t SMEM_TOTAL = OFF_MAXB + 64;      // ~100.7 KB
constexpr uint32_t D_AB = OFF_XB - OFF_XA;          // xA slot -> xB slot delta
constexpr uint32_t D_MB = OFF_MBB - OFF_MBA;        // mbA -> mbB delta
}

__device__ __forceinline__ uint32_t smem_u32(const void* p) {
    return (uint32_t)__cvta_generic_to_shared(p);
}

__device__ __forceinline__ uint32_t mapa_rank(uint32_t laddr, uint32_t rank) {
    uint32_t rem;
    asm volatile("mapa.shared::cluster.u32 %0, %1, %2;" : "=r"(rem) : "r"(laddr), "r"(rank));
    return rem;
}

__device__ __forceinline__ void st_cluster_f32_addr(uint32_t raddr, float v) {
    asm volatile("st.shared::cluster.f32 [%0], %1;" :: "r"(raddr), "f"(v) : "memory");
}

__device__ __forceinline__ void mbar_arrive_cluster(uint32_t raddr) {
    asm volatile("mbarrier.arrive.shared::cluster.b64 _, [%0];" :: "r"(raddr) : "memory");
}

__device__ __forceinline__ void mbar_wait(uint32_t addr, uint32_t phase) {
    asm volatile(
        "{\n\t"
        ".reg .pred P;\n\t"
        "WLOOP_%=:\n\t"
        "mbarrier.try_wait.parity.acquire.cluster.shared::cta.b64 P, [%0], %1, 0x989680;\n\t"
        "@P bra WDONE_%=;\n\t"
        "bra WLOOP_%=;\n\t"
        "WDONE_%=:\n\t"
        "}"
        :: "r"(addr), "r"(phase) : "memory");
}

__device__ __forceinline__ void fence_cluster() {
    asm volatile("fence.acq_rel.cluster;" ::: "memory");
}

__device__ __forceinline__ void cluster_sync_all() {
    asm volatile("barrier.cluster.arrive.aligned;" ::: "memory");
    asm volatile("barrier.cluster.wait.aligned;" ::: "memory");
}

__global__ void __launch_bounds__(THREADS, 1) __cluster_dims__(CSZ, 1, 1)
sinkhorn_kernel(const float* __restrict__ A, float* __restrict__ Out)
{
    extern __shared__ __align__(16) char smem[];
    float* dAp  = reinterpret_cast<float*>(smem + OFF_DA);
    float* dBp  = reinterpret_cast<float*>(smem + OFF_DB);
    float* xAp  = reinterpret_cast<float*>(smem + OFF_XA);   // [2][8][256]
    float* xBp  = reinterpret_cast<float*>(smem + OFF_XB);
    float* wsAp = reinterpret_cast<float*>(smem + OFF_WSA);  // [32][256]
    float* wsBp = reinterpret_cast<float*>(smem + OFF_WSB);
    float* redA = reinterpret_cast<float*>(smem + OFF_RED);
    float* redB = redA + NWARP;
    float* mxb  = reinterpret_cast<float*>(smem + OFF_MAXB); // [2][8]

    const uint32_t sbase = smem_u32(smem);
    const int tid  = threadIdx.x;
    const int w    = tid >> 5;
    const int l    = tid & 31;
    const int rank = blockIdx.x & (CSZ - 1);
    const int cl   = blockIdx.x >> 3;   // cluster id: matrices 2cl, 2cl+1

    const float* AmA = A   + (size_t)(2 * cl)     * N * N;
    const float* AmB = A   + (size_t)(2 * cl + 1) * N * N;
    float*       OmA = Out + (size_t)(2 * cl)     * N * N;
    float*       OmB = Out + (size_t)(2 * cl + 1) * N * N;

    if (tid == 0) {
        #pragma unroll
        for (int q = 0; q < 2; q++) {
            asm volatile("mbarrier.init.shared.b64 [%0], %1;"
                         :: "r"(sbase + OFF_MBA + q * 8), "r"(CSZ - 1) : "memory");
            asm volatile("mbarrier.init.shared.b64 [%0], %1;"
                         :: "r"(sbase + OFF_MBB + q * 8), "r"(CSZ - 1) : "memory");
        }
        asm volatile("fence.mbarrier_init.release.cluster;" ::: "memory");
    }

    // ---- row layout: warp w owns global row rank*32+w; lane l cols [8l,8l+8)
    const int grow = rank * ROWS + w;
    const int c0   = l * 8;

    float erA[8], erB[8];
    {
        float4 a0 = *(const float4*)(AmA + grow * N + c0);
        float4 a1 = *(const float4*)(AmA + grow * N + c0 + 4);
        erA[0]=a0.x; erA[1]=a0.y; erA[2]=a0.z; erA[3]=a0.w;
        erA[4]=a1.x; erA[5]=a1.y; erA[6]=a1.z; erA[7]=a1.w;
        float4 b0 = *(const float4*)(AmB + grow * N + c0);
        float4 b1 = *(const float4*)(AmB + grow * N + c0 + 4);
        erB[0]=b0.x; erB[1]=b0.y; erB[2]=b0.z; erB[3]=b0.w;
        erB[4]=b1.x; erB[5]=b1.y; erB[6]=b1.z; erB[7]=b1.w;
        #pragma unroll
        for (int k = 0; k < 8; k++) { erA[k] *= INV_TAU; erB[k] *= INV_TAU; }
    }

    // ---- per-matrix global max (stable E = exp(a/tau - m))
    {
        float ma = erA[0], mb = erB[0];
        #pragma unroll
        for (int k = 1; k < 8; k++) { ma = fmaxf(ma, erA[k]); mb = fmaxf(mb, erB[k]); }
        #pragma unroll
        for (int off = 16; off; off >>= 1) {
            ma = fmaxf(ma, __shfl_xor_sync(0xffffffffu, ma, off));
            mb = fmaxf(mb, __shfl_xor_sync(0xffffffffu, mb, off));
        }
        if (l == 0) { redA[w] = ma; redB[w] = mb; }
    }
    __syncthreads();
    if (w < 2) {
        float v = (w == 0) ? redA[l] : redB[l];
        #pragma unroll
        for (int off = 16; off; off >>= 1)
            v = fmaxf(v, __shfl_xor_sync(0xffffffffu, v, off));
        if (l == 0) {
            uint32_t slot = sbase + OFF_MAXB + (w * CSZ + rank) * 4;
            #pragma unroll
            for (int r = 0; r < CSZ; r++)
                st_cluster_f32_addr(mapa_rank(slot, (uint32_t)r), v);
        }
    }
    cluster_sync_all();   // orders max stores AND mbarrier inits cluster-wide
    float mA = mxb[0], mB = mxb[CSZ];
    #pragma unroll
    for (int r = 1; r < CSZ; r++) { mA = fmaxf(mA, mxb[r]); mB = fmaxf(mB, mxb[CSZ + r]); }

    #pragma unroll
    for (int k = 0; k < 8; k++) {
        erA[k] = __expf(erA[k] - mA);
        erB[k] = __expf(erB[k] - mB);
    }

    if (tid < N) { dAp[tid] = 1.0f; dBp[tid] = 1.0f; }
    __syncthreads();

    // ---- hoisted remote addresses
    // scatter bases: thread j (<256) pushes its col partial to 7 peers.
    // mapa is offset-preserving within a CTA's window, so xB/parity targets
    // derive from the xA base by constant deltas.
    uint32_t sA[CSZ - 1];
    if (tid < N) {
        uint32_t la = sbase + OFF_XA + (uint32_t)rank * 1024u + (uint32_t)tid * 4u;
        #pragma unroll
        for (int i = 0; i < CSZ - 1; i++)
            sA[i] = mapa_rank(la, (uint32_t)((rank + 1 + i) & (CSZ - 1)));
    }
    uint32_t rmbA = 0;
    if (w == 0 && l < CSZ - 1)
        rmbA = mapa_rank(sbase + OFF_MBA, (uint32_t)((rank + 1 + l) & (CSZ - 1)));

    float rsA = 1.0f, rsB = 1.0f;   // 1/rowsum for my row (persist for epilogue)

    #pragma unroll 1
    for (int it = 0; it < NITER; it++) {
        const uint32_t par    = (uint32_t)(it & 1);
        const uint32_t ph     = (uint32_t)((it >> 1) & 1);
        const uint32_t paroff = par * 8192u;   // [2][8][256] parity stride

        // ======== P1: A row pass + fused col partials ========
        {
            float4 d0 = *(const float4*)&dAp[c0];
            float4 d1 = *(const float4*)&dAp[c0 + 4];
            float s = erA[0]*d0.x + erA[1]*d0.y + erA[2]*d0.z + erA[3]*d0.w
                    + erA[4]*d1.x + erA[5]*d1.y + erA[6]*d1.z + erA[7]*d1.w;
            #pragma unroll
            for (int off = 16; off; off >>= 1)
                s += __shfl_xor_sync(0xffffffffu, s, off);
            rsA = __fdividef(1.0f, fmaxf(s, 1e-30f));
            float4 q0, q1;
            q0.x = erA[0]*rsA; q0.y = erA[1]*rsA; q0.z = erA[2]*rsA; q0.w = erA[3]*rsA;
            q1.x = erA[4]*rsA; q1.y = erA[5]*rsA; q1.z = erA[6]*rsA; q1.w = erA[7]*rsA;
            *(float4*)&wsAp[w * N + c0]     = q0;
            *(float4*)&wsAp[w * N + c0 + 4] = q1;
        }
        __syncthreads();

        // ======== P2: B row pass (all warps) || colsumA + scatterA (w 0-7) ==
        {
            float4 d0 = *(const float4*)&dBp[c0];
            float4 d1 = *(const float4*)&dBp[c0 + 4];
            float s = erB[0]*d0.x + erB[1]*d0.y + erB[2]*d0.z + erB[3]*d0.w
                    + erB[4]*d1.x + erB[5]*d1.y + erB[6]*d1.z + erB[7]*d1.w;
            #pragma unroll
            for (int off = 16; off; off >>= 1)
                s += __shfl_xor_sync(0xffffffffu, s, off);
            rsB = __fdividef(1.0f, fmaxf(s, 1e-30f));
            float4 q0, q1;
            q0.x = erB[0]*rsB; q0.y = erB[1]*rsB; q0.z = erB[2]*rsB; q0.w = erB[3]*rsB;
            q1.x = erB[4]*rsB; q1.y = erB[5]*rsB; q1.z = erB[6]*rsB; q1.w = erB[7]*rsB;
            *(float4*)&wsBp[w * N + c0]     = q0;
            *(float4*)&wsBp[w * N + c0 + 4] = q1;
        }
        float pownA = 0.0f;
        if (tid < N) {
            float f0 = 0.f, f1 = 0.f, f2 = 0.f, f3 = 0.f;
            #pragma unroll
            for (int w2 = 0; w2 < NWARP; w2 += 4) {
                f0 += wsAp[w2 * N + tid];       f1 += wsAp[(w2 + 1) * N + tid];
                f2 += wsAp[(w2 + 2) * N + tid]; f3 += wsAp[(w2 + 3) * N + tid];
            }
            pownA = (f0 + f1) + (f2 + f3);
            #pragma unroll
            for (int i = 0; i < CSZ - 1; i++)
                st_cluster_f32_addr(sA[i] + paroff, pownA);
        }
        __syncthreads();

        // ======== P3: publish A || colsumB + scatterB ========
        if (w == 0 && l < CSZ - 1) {
            fence_cluster();
            mbar_arrive_cluster(rmbA + par * 8);
        }
        float pownB = 0.0f;
        if (tid < N) {
            float f0 = 0.f, f1 = 0.f, f2 = 0.f, f3 = 0.f;
            #pragma unroll
            for (int w2 = 0; w2 < NWARP; w2 += 4) {
                f0 += wsBp[w2 * N + tid];       f1 += wsBp[(w2 + 1) * N + tid];
                f2 += wsBp[(w2 + 2) * N + tid]; f3 += wsBp[(w2 + 3) * N + tid];
            }
            pownB = (f0 + f1) + (f2 + f3);
            #pragma unroll
            for (int i = 0; i < CSZ - 1; i++)
                st_cluster_f32_addr(sA[i] + D_AB + paroff, pownB);
        }
        __syncthreads();

        // ======== P4: publish B || combine A then B (warps 0-7) ========
        if (w == 0 && l < CSZ - 1) {
            fence_cluster();
            mbar_arrive_cluster(rmbA + D_MB + par * 8);
        }
        if (tid < N) {
            // A's exchange has been in flight since P3 start -> near-free wait
            mbar_wait(sbase + OFF_MBA + par * 8, ph);
            float fa = pownA;
            #pragma unroll
            for (int i = 1; i < CSZ; i++) {
                int src = (rank + i) & (CSZ - 1);
                fa += xAp[paroff / 4 + src * N + tid];
            }
            dAp[tid] = __fdividef(1.0f, fmaxf(fa, 1e-30f));

            mbar_wait(sbase + OFF_MBB + par * 8, ph);
            float fb = pownB;
            #pragma unroll
            for (int i = 1; i < CSZ; i++) {
                int src = (rank + i) & (CSZ - 1);
                fb += xBp[paroff / 4 + src * N + tid];
            }
            dBp[tid] = __fdividef(1.0f, fmaxf(fb, 1e-30f));
        }
        __syncthreads();
    }

    // ======== epilogue: P = E * e[i] * d[j] for both matrices ========
    {
        float4 d0 = *(const float4*)&dAp[c0];
        float4 d1 = *(const float4*)&dAp[c0 + 4];
        float4 o0, o1;
        o0.x = erA[0]*rsA*d0.x; o0.y = erA[1]*rsA*d0.y;
        o0.z = erA[2]*rsA*d0.z; o0.w = erA[3]*rsA*d0.w;
        o1.x = erA[4]*rsA*d1.x; o1.y = erA[5]*rsA*d1.y;
        o1.z = erA[6]*rsA*d1.z; o1.w = erA[7]*rsA*d1.w;
        *(float4*)(OmA + grow * N + c0)     = o0;
        *(float4*)(OmA + grow * N + c0 + 4) = o1;
    }
    {
        float4 d0 = *(const float4*)&dBp[c0];
        float4 d1 = *(const float4*)&dBp[c0 + 4];
        float4 o0, o1;
        o0.x = erB[0]*rsB*d0.x; o0.y = erB[1]*rsB*d0.y;
        o0.z = erB[2]*rsB*d0.z; o0.w = erB[3]*rsB*d0.w;
        o1.x = erB[4]*rsB*d1.x; o1.y = erB[5]*rsB*d1.y;
        o1.z = erB[6]*rsB*d1.z; o1.w = erB[7]*rsB*d1.w;
        *(float4*)(OmB + grow * N + c0)     = o0;
        *(float4*)(OmB + grow * N + c0 + 4) = o1;
    }

    // keep all CTAs alive until every in-flight remote store is consumed
    cluster_sync_all();
}

extern "C" void kernel_launch(void* const* d_in, const int* in_sizes, int n_in,
                              void* d_out, int out_size) {
    const float* alpha = (const float*)d_in[0];
    float* out = (float*)d_out;
    cudaFuncSetAttribute(sinkhorn_kernel,
                         cudaFuncAttributeMaxDynamicSharedMemorySize, SMEM_TOTAL);
    sinkhorn_kernel<<<(NMAT / 2) * CSZ, THREADS, SMEM_TOTAL>>>(alpha, out);
}